// round 17
// baseline (speedup 1.0000x reference)
#include <cuda_runtime.h>
#include <cuda_fp16.h>

#define NN 50000
#define NE 800000
#define D  128
#define NG 128

#define SA 132     // pool-staging row stride (floats)
#define SW 136     // fp16 row stride for A tile (272B rows -> conflict-free LDSM)
#define TM 32      // tile rows
#define PGRID 296  // 148 SMs x 2 blocks
#define NTILES ((NN + TM - 1) / TM)   // 1563

// ---------------- device scratch ----------------
__device__ __half g_h0[NN * D];
__device__ __half g_hA[NN * D];
__device__ __half g_hB[NN * D];
__device__ int   g_beg[NN];
__device__ int   g_pos[NN];
__device__ int   g_cnt[NN];
__device__ int   g_col[NE];
__device__ int   g_total;
__device__ uint4 g_wfrag[3][2][16][8][32];

#define SCAN_B 98
#define WFRAG_N (6 * 16 * 8 * 32)
#define FCONV_N (NN * D / 4)

__device__ __forceinline__ unsigned sp2h(float2 x, unsigned& lo) {
    __half2 h = __floats2half2_rn(x.x, x.y);
    unsigned hu = *reinterpret_cast<unsigned*>(&h);
    float2 hf = __half22float2(h);
    __half2 l = __floats2half2_rn(x.x - hf.x, x.y - hf.y);
    lo = *reinterpret_cast<unsigned*>(&l);
    return hu;
}

__global__ void k_init(const float* __restrict__ feats,
                       const float* __restrict__ W10, const float* __restrict__ W20,
                       const float* __restrict__ W11, const float* __restrict__ W21,
                       const float* __restrict__ W12, const float* __restrict__ W22,
                       float* __restrict__ out) {
    int i = blockIdx.x * 256 + threadIdx.x;
    if (i < FCONV_N) {
        int j = i * 4;
        float4 v = __ldg((const float4*)&feats[j]);
        __half2 h0 = __floats2half2_rn(v.x, v.y);
        __half2 h1 = __floats2half2_rn(v.z, v.w);
        *(uint2*)&g_h0[j] = make_uint2(*(unsigned*)&h0, *(unsigned*)&h1);
    } else if (i < FCONV_N + WFRAG_N) {
        int w = i - FCONV_N;
        int which = w >> 12;
        int rem   = w & 4095;
        int cb    = rem >> 8;
        int kk    = (rem >> 5) & 7;
        int lane  = rem & 31;
        int grp = lane >> 2, qid = lane & 3;
        const float* W = (which == 0) ? W10 : (which == 1) ? W20 : (which == 2) ? W11
                        : (which == 3) ? W21 : (which == 4) ? W12 : W22;
        int layer = which >> 1, g = which & 1;
        int n  = cb * 8 + grp;
        int k0 = kk * 16 + 2 * qid;
        float x0 = __ldg(&W[(k0)     * 128 + n]);
        float x1 = __ldg(&W[(k0 + 1) * 128 + n]);
        float x2 = __ldg(&W[(k0 + 8) * 128 + n]);
        float x3 = __ldg(&W[(k0 + 9) * 128 + n]);
        unsigned bl0, bl1;
        unsigned bh0 = sp2h(make_float2(x0, x1), bl0);
        unsigned bh1 = sp2h(make_float2(x2, x3), bl1);
        g_wfrag[layer][g][cb][kk][lane] = make_uint4(bh0, bh1, bl0, bl1);
    } else if (i < FCONV_N + WFRAG_N + NN) {
        g_cnt[i - FCONV_N - WFRAG_N] = 0;
    } else if (i < FCONV_N + WFRAG_N + NN + NG * D) {
        out[i - FCONV_N - WFRAG_N - NN] = 0.f;
    } else if (i == FCONV_N + WFRAG_N + NN + NG * D) {
        g_total = 0;
    }
}

// ---------------- CSR build (R13 form) ----------------
__global__ void k_count(const int* __restrict__ dst) {
    int e4 = blockIdx.x * blockDim.x + threadIdx.x;
    if (e4 * 4 < NE) {
        int4 d = __ldg((const int4*)dst + e4);
        atomicAdd(&g_cnt[d.x], 1);
        atomicAdd(&g_cnt[d.y], 1);
        atomicAdd(&g_cnt[d.z], 1);
        atomicAdd(&g_cnt[d.w], 1);
    }
}

__global__ void k_assign() {
    int t = threadIdx.x, b = blockIdx.x;
    int i = b * 512 + t;
    int v = (i < NN) ? g_cnt[i] : 0;
    int x = v;
    #pragma unroll
    for (int o = 1; o < 32; o <<= 1) {
        int y = __shfl_up_sync(0xffffffffu, x, o);
        if ((t & 31) >= o) x += y;
    }
    __shared__ int ws[16];
    __shared__ int sbase;
    if ((t & 31) == 31) ws[t >> 5] = x;
    __syncthreads();
    if (t < 16) {
        int y = ws[t];
        #pragma unroll
        for (int o = 1; o < 16; o <<= 1) {
            int z = __shfl_up_sync(0xffffu, y, o);
            if (t >= o) y += z;
        }
        ws[t] = y;
    }
    __syncthreads();
    int off = (t >= 32) ? ws[(t >> 5) - 1] : 0;
    int incl = x + off;
    if (t == 511) sbase = atomicAdd(&g_total, incl);
    __syncthreads();
    if (i < NN) {
        int p = sbase + incl - v;
        g_beg[i] = p;
        g_pos[i] = p;
    }
}

__global__ void k_scatter(const int* __restrict__ src, const int* __restrict__ dst) {
    int e4 = blockIdx.x * blockDim.x + threadIdx.x;
    if (e4 * 4 < NE) {
        int4 d = __ldg((const int4*)dst + e4);
        int4 s = __ldg((const int4*)src + e4);
        g_col[atomicAdd(&g_pos[d.x], 1)] = s.x;
        g_col[atomicAdd(&g_pos[d.y], 1)] = s.y;
        g_col[atomicAdd(&g_pos[d.z], 1)] = s.z;
        g_col[atomicAdd(&g_pos[d.w], 1)] = s.w;
    }
}

// ---------------- warp-specialized fused layer ----------------
// smem: As0, As1 (fp16 [TM][SW] each) + pool staging (fp32 [TM][SA])
#define LAYER_SMEM (2 * TM * SW * 2 + TM * SA * 4)   // 17408 + 16896 = 34304

#define NB_SYNC(id)   asm volatile("bar.sync %0, 512;"   :: "r"(id) : "memory")
#define NB_ARRIVE(id) asm volatile("bar.arrive %0, 512;" :: "r"(id) : "memory")
#define NB_CONS()     asm volatile("bar.sync 5, 256;"    ::: "memory")
// ids: FULL[b] = 1+b, EMPTY[b] = 3+b, consumer-internal = 5

__device__ __forceinline__ void mma_f16(float* c, const unsigned* a, const unsigned* b) {
    asm volatile("mma.sync.aligned.m16n8k16.row.col.f32.f16.f16.f32 "
        "{%0,%1,%2,%3}, {%4,%5,%6,%7}, {%8,%9}, {%0,%1,%2,%3};"
        : "+f"(c[0]), "+f"(c[1]), "+f"(c[2]), "+f"(c[3])
        : "r"(a[0]), "r"(a[1]), "r"(a[2]), "r"(a[3]), "r"(b[0]), "r"(b[1]));
}

__device__ __forceinline__ void ldsm4(unsigned* r, unsigned addr) {
    asm volatile("ldmatrix.sync.aligned.m8n8.x4.shared.b16 {%0,%1,%2,%3}, [%4];"
        : "=r"(r[0]), "=r"(r[1]), "=r"(r[2]), "=r"(r[3]) : "r"(addr));
}

__device__ __forceinline__ uint2 ldcg2(const uint2* p) {
    uint2 v;
    asm volatile("ld.global.cg.v2.u32 {%0,%1}, [%2];" : "=r"(v.x), "=r"(v.y) : "l"(p));
    return v;
}

__device__ __forceinline__ void acc4(float4& a, uint2 u) {
    float2 f0 = __half22float2(*reinterpret_cast<__half2*>(&u.x));
    float2 f1 = __half22float2(*reinterpret_cast<__half2*>(&u.y));
    a.x += f0.x; a.y += f0.y; a.z += f1.x; a.w += f1.y;
}

__global__ void __launch_bounds__(512, 2)
k_layer(const __half* __restrict__ hin, const float* __restrict__ eps, int layer,
        const float* __restrict__ B1, const float* __restrict__ B2,
        __half* __restrict__ hout,
        const int* __restrict__ gid, float* __restrict__ out) {
    extern __shared__ float sm[];
    __half* As0 = (__half*)sm;
    __half* As1 = As0 + TM * SW;
    float*  Ps  = (float*)(As1 + TM * SW);   // pool staging [TM][SA]

    const int t    = threadIdx.x;
    const int wid  = t >> 5;        // 0..15
    const int lane = t & 31;
    const bool producer = (wid < 8);

    const float ev = 1.0f + __ldg(&eps[layer]);

    // consumer constants
    const int cw  = wid - 8;        // 0..7 -> col group cw*16..+15
    const int grp = lane >> 2;
    const int qid = lane & 3;
    const unsigned frag_pat = (((lane & 7) + ((lane >> 3) & 1) * 8) * SW + ((lane >> 4) * 8)) * 2;
    const unsigned base0 = (unsigned)__cvta_generic_to_shared(As0) + frag_pat;
    const unsigned base1 = (unsigned)__cvta_generic_to_shared(As1) + frag_pat;

    int i = 0;
    for (int tile = blockIdx.x; tile < NTILES; tile += PGRID, i++) {
        const int b = i & 1;
        const int row0 = tile * TM;
        __half* buf = b ? As1 : As0;

        if (producer) {
            // ---- wait consumers freed this buffer (skip for first two fills) ----
            if (i >= 2) NB_SYNC(3 + b);

            const uint2* hv = (const uint2*)hin;
            #pragma unroll
            for (int k = 0; k < 4; k++) {
                int r = wid + 8 * k;
                int node = row0 + r;
                float4 a = make_float4(0.f, 0.f, 0.f, 0.f);
                if (node < NN) {
                    acc4(a, ldcg2(&hv[node * 32 + lane]));
                    a.x *= ev; a.y *= ev; a.z *= ev; a.w *= ev;
                    int jb = g_beg[node];
                    int je = jb + g_cnt[node];
                    int j = jb;
                    for (; j + 8 <= je; j += 8) {
                        int s0 = g_col[j],     s1 = g_col[j + 1], s2 = g_col[j + 2], s3 = g_col[j + 3];
                        int s4 = g_col[j + 4], s5 = g_col[j + 5], s6 = g_col[j + 6], s7 = g_col[j + 7];
                        uint2 x0 = ldcg2(&hv[s0 * 32 + lane]);
                        uint2 x1 = ldcg2(&hv[s1 * 32 + lane]);
                        uint2 x2 = ldcg2(&hv[s2 * 32 + lane]);
                        uint2 x3 = ldcg2(&hv[s3 * 32 + lane]);
                        uint2 x4 = ldcg2(&hv[s4 * 32 + lane]);
                        uint2 x5 = ldcg2(&hv[s5 * 32 + lane]);
                        uint2 x6 = ldcg2(&hv[s6 * 32 + lane]);
                        uint2 x7 = ldcg2(&hv[s7 * 32 + lane]);
                        acc4(a, x0); acc4(a, x1); acc4(a, x2); acc4(a, x3);
                        acc4(a, x4); acc4(a, x5); acc4(a, x6); acc4(a, x7);
                    }
                    for (; j + 4 <= je; j += 4) {
                        int s0 = g_col[j], s1 = g_col[j + 1], s2 = g_col[j + 2], s3 = g_col[j + 3];
                        uint2 x0 = ldcg2(&hv[s0 * 32 + lane]);
                        uint2 x1 = ldcg2(&hv[s1 * 32 + lane]);
                        uint2 x2 = ldcg2(&hv[s2 * 32 + lane]);
                        uint2 x3 = ldcg2(&hv[s3 * 32 + lane]);
                        acc4(a, x0); acc4(a, x1); acc4(a, x2); acc4(a, x3);
                    }
                    for (; j < je; j++) acc4(a, ldcg2(&hv[g_col[j] * 32 + lane]));
                }
                __half2 h0 = __floats2half2_rn(a.x, a.y);
                __half2 h1 = __floats2half2_rn(a.z, a.w);
                *(uint2*)&buf[r * SW + lane * 4] = make_uint2(*(unsigned*)&h0, *(unsigned*)&h1);
            }
            NB_ARRIVE(1 + b);    // buffer full
        } else {
            // ---- wait buffer full ----
            NB_SYNC(1 + b);
            const unsigned lds_base = b ? base1 : base0;

            float acc[2][2][4];
            #pragma unroll
            for (int mt = 0; mt < 2; mt++)
                #pragma unroll
                for (int nt = 0; nt < 2; nt++)
                    #pragma unroll
                    for (int q = 0; q < 4; q++) acc[mt][nt][q] = 0.f;

            // GEMM 1
            #pragma unroll 2
            for (int kk = 0; kk < 8; kk++) {
                unsigned ah[2][4];
                #pragma unroll
                for (int mt = 0; mt < 2; mt++)
                    ldsm4(ah[mt], lds_base + (mt * 16 * SW + kk * 16) * 2);
                #pragma unroll
                for (int nt = 0; nt < 2; nt++) {
                    uint4 f = __ldg(&g_wfrag[layer][0][cw * 2 + nt][kk][lane]);
                    unsigned bh[2] = {f.x, f.y};
                    unsigned bl[2] = {f.z, f.w};
                    #pragma unroll
                    for (int mt = 0; mt < 2; mt++) {
                        mma_f16(acc[mt][nt], ah[mt], bh);
                        mma_f16(acc[mt][nt], ah[mt], bl);
                    }
                }
            }
            NB_CONS();   // GEMM1 reads done before epi1 writes (WAR)

            __half* bb = b ? As1 : As0;
            #pragma unroll
            for (int mt = 0; mt < 2; mt++) {
                int r0 = mt * 16 + grp;
                #pragma unroll
                for (int nt = 0; nt < 2; nt++) {
                    int c = cw * 16 + nt * 8 + qid * 2;
                    float b0 = __ldg(&B1[c]);
                    float b1v = __ldg(&B1[c + 1]);
                    __half2 v0 = __floats2half2_rn(fmaxf(acc[mt][nt][0] + b0, 0.f),
                                                   fmaxf(acc[mt][nt][1] + b1v, 0.f));
                    __half2 v1 = __floats2half2_rn(fmaxf(acc[mt][nt][2] + b0, 0.f),
                                                   fmaxf(acc[mt][nt][3] + b1v, 0.f));
                    *(unsigned*)&bb[r0 * SW + c] = *(unsigned*)&v0;
                    *(unsigned*)&bb[(r0 + 8) * SW + c] = *(unsigned*)&v1;
                }
            }
            NB_CONS();   // epi1 writes visible before GEMM2 reads (RAW)

            #pragma unroll
            for (int mt = 0; mt < 2; mt++)
                #pragma unroll
                for (int nt = 0; nt < 2; nt++)
                    #pragma unroll
                    for (int q = 0; q < 4; q++) acc[mt][nt][q] = 0.f;

            // GEMM 2
            #pragma unroll 2
            for (int kk = 0; kk < 8; kk++) {
                unsigned ah[2][4];
                #pragma unroll
                for (int mt = 0; mt < 2; mt++)
                    ldsm4(ah[mt], lds_base + (mt * 16 * SW + kk * 16) * 2);
                #pragma unroll
                for (int nt = 0; nt < 2; nt++) {
                    uint4 f = __ldg(&g_wfrag[layer][1][cw * 2 + nt][kk][lane]);
                    unsigned bh[2] = {f.x, f.y};
                    unsigned bl[2] = {f.z, f.w};
                    #pragma unroll
                    for (int mt = 0; mt < 2; mt++) {
                        mma_f16(acc[mt][nt], ah[mt], bh);
                        mma_f16(acc[mt][nt], ah[mt], bl);
                    }
                }
            }

            if (hout) {
                #pragma unroll
                for (int mt = 0; mt < 2; mt++) {
                    int r0 = row0 + mt * 16 + grp;
                    #pragma unroll
                    for (int nt = 0; nt < 2; nt++) {
                        int c = cw * 16 + nt * 8 + qid * 2;
                        float b0 = __ldg(&B2[c]);
                        float b1v = __ldg(&B2[c + 1]);
                        if (r0 < NN) {
                            __half2 o = __floats2half2_rn(acc[mt][nt][0] + b0, acc[mt][nt][1] + b1v);
                            *(unsigned*)&hout[r0 * 128 + c] = *(unsigned*)&o;
                        }
                        if (r0 + 8 < NN) {
                            __half2 o = __floats2half2_rn(acc[mt][nt][2] + b0, acc[mt][nt][3] + b1v);
                            *(unsigned*)&hout[(r0 + 8) * 128 + c] = *(unsigned*)&o;
                        }
                    }
                }
            } else {
                // pool: stage fp32 into Ps (separate buffer), consumer-sync, run-length atomics
                #pragma unroll
                for (int mt = 0; mt < 2; mt++) {
                    int r0 = mt * 16 + grp;
                    #pragma unroll
                    for (int nt = 0; nt < 2; nt++) {
                        int c = cw * 16 + nt * 8 + qid * 2;
                        float b0 = __ldg(&B2[c]);
                        float b1v = __ldg(&B2[c + 1]);
                        *(float2*)&Ps[r0 * SA + c] =
                            make_float2(acc[mt][nt][0] + b0, acc[mt][nt][1] + b1v);
                        *(float2*)&Ps[(r0 + 8) * SA + c] =
                            make_float2(acc[mt][nt][2] + b0, acc[mt][nt][3] + b1v);
                    }
                }
                NB_CONS();
                int ct = t - 256;          // 0..255
                int gg = ct >> 7;          // 2 groups of 16 rows
                int c  = ct & 127;
                float pacc = 0.f;
                int cur = -1;
                for (int r = gg * 16; r < gg * 16 + 16; r++) {
                    int node = row0 + r;
                    if (node >= NN) break;
                    int g = __ldg(&gid[node]);
                    if (g != cur) {
                        if (cur >= 0) atomicAdd(&out[cur * 128 + c], pacc);
                        cur = g;
                        pacc = 0.f;
                    }
                    pacc += Ps[r * SA + c];
                }
                if (cur >= 0) atomicAdd(&out[cur * 128 + c], pacc);
            }
            NB_ARRIVE(3 + b);   // buffer empty
        }
    }
}

// ---------------- launch ----------------
extern "C" void kernel_launch(void* const* d_in, const int* in_sizes, int n_in,
                              void* d_out, int out_size) {
    const float* feats = (const float*)d_in[0];
    const int*   esrc  = (const int*)d_in[1];
    const int*   edst  = (const int*)d_in[2];
    const int*   gid   = (const int*)d_in[3];
    const float* eps   = (const float*)d_in[4];
    const float* W1[3] = {(const float*)d_in[5],  (const float*)d_in[9],  (const float*)d_in[13]};
    const float* B1[3] = {(const float*)d_in[6],  (const float*)d_in[10], (const float*)d_in[14]};
    const float* W2[3] = {(const float*)d_in[7],  (const float*)d_in[11], (const float*)d_in[15]};
    const float* B2[3] = {(const float*)d_in[8],  (const float*)d_in[12], (const float*)d_in[16]};
    float* out = (float*)d_out;
    (void)in_sizes; (void)n_in; (void)out_size;

    cudaFuncSetAttribute(k_layer, cudaFuncAttributeMaxDynamicSharedMemorySize, LAYER_SMEM);

    __half* h0; cudaGetSymbolAddress((void**)&h0, g_h0);
    __half* hA; cudaGetSymbolAddress((void**)&hA, g_hA);
    __half* hB; cudaGetSymbolAddress((void**)&hB, g_hB);

    int initN = FCONV_N + WFRAG_N + NN + NG * D + 1;
    k_init<<<(initN + 255) / 256, 256>>>(feats, W1[0], W2[0], W1[1], W2[1], W1[2], W2[2], out);

    k_count<<<(NE / 4 + 255) / 256, 256>>>(edst);
    k_assign<<<SCAN_B, 512>>>();
    k_scatter<<<(NE / 4 + 255) / 256, 256>>>(esrc, edst);

    k_layer<<<PGRID, 512, LAYER_SMEM>>>(h0, eps, 0, B1[0], B2[0], hA, gid, out);
    k_layer<<<PGRID, 512, LAYER_SMEM>>>(hA, eps, 1, B1[1], B2[1], hB, gid, out);
    k_layer<<<PGRID, 512, LAYER_SMEM>>>(hB, eps, 2, B1[2], B2[2], nullptr, gid, out);
}